// round 6
// baseline (speedup 1.0000x reference)
#include <cuda_runtime.h>
#include <math.h>
#include <stdint.h>

#define BATCH   512
#define STEPS   128
#define TSTEPS  255          // 127 history + 128 action
#define DIN     256
#define UDIM    256
#define G4      1024         // 4*UDIM

// Recurrence geometry: 16 clusters x 8 CTAs, 4 rows/CTA, 512 threads
#define CLSZ    8
#define RC      128                          // CTAs total
#define RR      4                            // rows per CTA
#define RTH     512                          // 256 features x 2 row-pairs
#define NSLOT   3                            // smem ring slots
#define KPS     16                           // k-rows per stage
#define SPS     (UDIM / KPS)                 // 16 stages per step
#define TOTSTG  (TSTEPS * SPS)               // 4080
#define STG_BYTES   (KPS * 256 * 16)         // 65536
#define SLICE_BYTES (STG_BYTES / CLSZ)       // 8192
#define HS_OFF  (NSLOT * STG_BYTES)          // 196608
#define MB_OFF  (HS_OFF + RR * 256 * 8)      // 204800
#define RSMEM   (MB_OFF + 128)               // 204928

// Scratch (static device allocations — no cudaMalloc anywhere)
__device__ float  g_state[BATCH * UDIM];
__device__ float  g_h[BATCH * UDIM];
__device__ float  g_G[(size_t)TSTEPS * BATCH * G4];   // x@Wk + bl, [t][b][4U]
__device__ float4 g_W4[256 * 256];                    // Wrk: (wi,wf,wg,wo) per (k,n)

// ---------------------------------------------------------------------------
// f32x2 packed-FMA helpers (sm_103a FFMA2 — only reachable via PTX)
// ---------------------------------------------------------------------------
union F2U { float2 f; unsigned long long u; };
union F4U { float4 f; ulonglong2 u; };

__device__ __forceinline__ void fma2(unsigned long long& d,
                                     unsigned long long a,
                                     unsigned long long b)
{
    asm("fma.rn.f32x2 %0, %1, %2, %0;" : "+l"(d) : "l"(a), "l"(b));
}
__device__ __forceinline__ unsigned long long dup2(float x)
{
    F2U t; t.f = make_float2(x, x); return t.u;
}
__device__ __forceinline__ float tanha(float x)
{
    float y; asm("tanh.approx.f32 %0, %1;" : "=f"(y) : "f"(x)); return y;
}
__device__ __forceinline__ float sigm(float x)
{
    return fmaf(0.5f, tanha(0.5f * x), 0.5f);
}
__device__ __forceinline__ uint32_t smem_u32(const void* p)
{
    uint32_t a;
    asm("{ .reg .u64 t; cvta.to.shared.u64 t, %1; cvt.u32.u64 %0, t; }"
        : "=r"(a) : "l"(p));
    return a;
}

// ---------------------------------------------------------------------------
// mbarrier + bulk-multicast helpers
// ---------------------------------------------------------------------------
__device__ __forceinline__ void mbar_init(uint32_t a, uint32_t cnt)
{
    asm volatile("mbarrier.init.shared.b64 [%0], %1;" :: "r"(a), "r"(cnt) : "memory");
}
__device__ __forceinline__ void mbar_expect(uint32_t a, uint32_t tx)
{
    asm volatile("mbarrier.arrive.expect_tx.shared.b64 _, [%0], %1;"
                 :: "r"(a), "r"(tx) : "memory");
}
__device__ __forceinline__ void mbar_arrive_rank(uint32_t a, uint32_t rank)
{
    asm volatile(
        "{\n\t.reg .b32 r;\n\t"
        "mapa.shared::cluster.u32 r, %0, %1;\n\t"
        "mbarrier.arrive.shared::cluster.b64 _, [r];\n\t}"
        :: "r"(a), "r"(rank) : "memory");
}
__device__ __forceinline__ void mbar_wait_acq(uint32_t a, uint32_t ph)
{
    asm volatile(
        "{\n\t.reg .pred P;\n\t"
        "WL%=:\n\t"
        "mbarrier.try_wait.parity.acquire.cta.shared::cta.b64 P, [%0], %1, 0x989680;\n\t"
        "@P bra WD%=;\n\t"
        "bra WL%=;\n\t"
        "WD%=:\n\t}"
        :: "r"(a), "r"(ph) : "memory");
}
__device__ __forceinline__ void mbar_wait_rlx(uint32_t a, uint32_t ph)
{
    asm volatile(
        "{\n\t.reg .pred P;\n\t"
        "WL%=:\n\t"
        "mbarrier.try_wait.parity.relaxed.cta.shared::cta.b64 P, [%0], %1, 0x989680;\n\t"
        "@P bra WD%=;\n\t"
        "bra WL%=;\n\t"
        "WD%=:\n\t}"
        :: "r"(a), "r"(ph) : "memory");
}
__device__ __forceinline__ void bulk_mc(uint32_t dst, const void* src, uint32_t bytes,
                                        uint32_t mbar, uint16_t mask)
{
    asm volatile(
        "cp.async.bulk.shared::cluster.global.mbarrier::complete_tx::bytes"
        ".multicast::cluster [%0], [%1], %2, [%3], %4;"
        :: "r"(dst), "l"(src), "r"(bytes), "r"(mbar), "h"(mask) : "memory");
}

// ---------------------------------------------------------------------------
// K0: reformat Wrk [256,1024] -> W4[k][n] = (wi,wf,wg,wo)
// ---------------------------------------------------------------------------
__global__ void reformat_wrk(const float* __restrict__ Wrk)
{
    const int idx = blockIdx.x * 256 + threadIdx.x;   // 65536
    const int k = idx >> 8, n = idx & 255;
    const float* w = Wrk + k * G4 + n;
    g_W4[idx] = make_float4(w[0], w[256], w[512], w[768]);
}

// ---------------------------------------------------------------------------
// K1: preamble — ms/rs/re/im + combine -> state [512,256]
// ---------------------------------------------------------------------------
__global__ void __launch_bounds__(256) preamble_kernel(
    const float* __restrict__ motion, const float* __restrict__ robot,
    const float* __restrict__ osr,    const float* __restrict__ osi,
    const float* __restrict__ orr_,   const float* __restrict__ ori_,
    const float* __restrict__ Wm, const float* __restrict__ bm,
    const float* __restrict__ Wr, const float* __restrict__ br,
    const float* __restrict__ Wre, const float* __restrict__ bre,
    const float* __restrict__ Wim, const float* __restrict__ bim,
    const float* __restrict__ Wc,  const float* __restrict__ bc)
{
    __shared__ float comb[768];
    const int row = blockIdx.x;
    const int n   = threadIdx.x;

    float s = bm[n];
    #pragma unroll 8
    for (int k = 0; k < 64; k++) s += motion[row*64 + k] * Wm[k*256 + n];
    comb[n] = fmaxf(s, 0.f);

    s = br[n];
    #pragma unroll 8
    for (int k = 0; k < 128; k++) s += robot[row*128 + k] * Wr[k*256 + n];
    comb[256 + n] = fmaxf(s, 0.f);

    if (n < 128) {
        float s3 = bre[n];
        #pragma unroll 8
        for (int k = 0; k < 64; k++) s3 += osr [row*64 + k] * Wre[k*128 + n];
        #pragma unroll 8
        for (int k = 0; k < 64; k++) s3 += orr_[row*64 + k] * Wre[(64+k)*128 + n];
        comb[512 + n] = fmaxf(s3, 0.f);
    } else {
        const int m = n - 128;
        float s4 = bim[m];
        #pragma unroll 8
        for (int k = 0; k < 64; k++) s4 += osi [row*64 + k] * Wim[k*128 + m];
        #pragma unroll 8
        for (int k = 0; k < 64; k++) s4 += ori_[row*64 + k] * Wim[(64+k)*128 + m];
        comb[640 + m] = fmaxf(s4, 0.f);
    }
    __syncthreads();

    float s5 = bc[n];
    #pragma unroll 8
    for (int k = 0; k < 768; k++) s5 += comb[k] * Wc[k*256 + n];
    g_state[row*256 + n] = fmaxf(s5, 0.f);
}

// ---------------------------------------------------------------------------
// K2: G = x @ Wk + bl.  M=130560, K=256, N=1024.
// 128x128 tile, BK=16, 256 threads, 8x8 microtile, FFMA2, reg-prefetch.
// ---------------------------------------------------------------------------
__global__ void __launch_bounds__(256, 1) xwk_kernel(
    const float* __restrict__ hist, const float* __restrict__ act,
    const float* __restrict__ Wk,   const float* __restrict__ bl)
{
    __shared__ float As[16][132];
    __shared__ float Bs[16][128];

    const int tid = threadIdx.x;
    const int tx  = tid & 15, ty = tid >> 4;
    const int bm0 = blockIdx.y * 128;
    const int bn0 = blockIdx.x * 128;

    const int ra = tid >> 2;
    const int kc = (tid & 3) * 4;
    const int mA0 = bm0 + ra, mA1 = bm0 + ra + 64;
    const int tA0 = mA0 >> 9, bA0 = mA0 & 511;
    const int tA1 = mA1 >> 9, bA1 = mA1 & 511;
    const float* arow0 = (tA0 < 127)
        ? (hist + ((size_t)bA0 * STEPS + tA0) * DIN)
        : (act  + ((size_t)bA0 * STEPS + (tA0 - 127)) * DIN);
    const float* arow1 = (tA1 < 127)
        ? (hist + ((size_t)bA1 * STEPS + tA1) * DIN)
        : (act  + ((size_t)bA1 * STEPS + (tA1 - 127)) * DIN);

    const int kb = tid >> 4;
    const int nb = (tid & 15) * 4;
    const float* bsrc = Wk + (size_t)kb * G4 + bn0 + nb;

    unsigned long long acc[8][4];
    #pragma unroll
    for (int i = 0; i < 8; i++)
        #pragma unroll
        for (int j = 0; j < 4; j++) acc[i][j] = 0ull;

    float4 a0 = *(const float4*)(arow0 + kc);
    float4 a1 = *(const float4*)(arow1 + kc);
    float4 b0 = *(const float4*)(bsrc);
    float4 b1 = *(const float4*)(bsrc + 64);

    for (int k0 = 0; k0 < 256; k0 += 16) {
        __syncthreads();
        As[kc+0][ra] = a0.x; As[kc+1][ra] = a0.y; As[kc+2][ra] = a0.z; As[kc+3][ra] = a0.w;
        As[kc+0][ra+64] = a1.x; As[kc+1][ra+64] = a1.y; As[kc+2][ra+64] = a1.z; As[kc+3][ra+64] = a1.w;
        *(float4*)&Bs[kb][nb]      = b0;
        *(float4*)&Bs[kb][nb + 64] = b1;
        __syncthreads();

        if (k0 + 16 < 256) {
            a0 = *(const float4*)(arow0 + k0 + 16 + kc);
            a1 = *(const float4*)(arow1 + k0 + 16 + kc);
            b0 = *(const float4*)(bsrc + (size_t)(k0 + 16) * G4);
            b1 = *(const float4*)(bsrc + (size_t)(k0 + 16) * G4 + 64);
        }

        #pragma unroll
        for (int k = 0; k < 16; k++) {
            float4 av0 = *(const float4*)&As[k][ty*8];
            float4 av1 = *(const float4*)&As[k][ty*8 + 4];
            F4U bv0, bv1;
            bv0.f = *(const float4*)&Bs[k][tx*8];
            bv1.f = *(const float4*)&Bs[k][tx*8 + 4];
            unsigned long long bp[4] = { bv0.u.x, bv0.u.y, bv1.u.x, bv1.u.y };
            float afl[8] = { av0.x, av0.y, av0.z, av0.w, av1.x, av1.y, av1.z, av1.w };
            #pragma unroll
            for (int i = 0; i < 8; i++) {
                unsigned long long ad = dup2(afl[i]);
                #pragma unroll
                for (int j = 0; j < 4; j++) fma2(acc[i][j], ad, bp[j]);
            }
        }
    }

    float blv[8];
    #pragma unroll
    for (int j = 0; j < 8; j++) blv[j] = bl[bn0 + tx*8 + j];

    #pragma unroll
    for (int i = 0; i < 8; i++) {
        const int m = bm0 + ty*8 + i;
        float v[8];
        #pragma unroll
        for (int j = 0; j < 4; j++) {
            F2U e; e.u = acc[i][j];
            v[j*2]   = e.f.x + blv[j*2];
            v[j*2+1] = e.f.y + blv[j*2+1];
        }
        float* dst = g_G + (size_t)m * G4 + bn0 + tx*8;
        *(float4*)dst       = make_float4(v[0], v[1], v[2], v[3]);
        *(float4*)(dst + 4) = make_float4(v[4], v[5], v[6], v[7]);
    }
}

// ---------------------------------------------------------------------------
// K3: LSTM recurrence — 16 clusters x 8 CTAs, 4 rows/CTA, 512 threads.
// W streamed via multicast TMA (cooperative slicing: each CTA loads 8KB,
// multicast to all 8) through a 3-slot x 64KB smem ring. Full/empty mbarrier
// handshake only (no barrier.cluster in the loop). Thread (n, rp): 2 rows x
// feature n, (i,f)/(g,o) packed in f32x2 lanes.
// ---------------------------------------------------------------------------
__global__ void __launch_bounds__(RTH, 1) __cluster_dims__(CLSZ, 1, 1)
recur_mc_kernel()
{
    extern __shared__ char smem[];
    float4* ws = (float4*)smem;                      // ring [3][16][256] float4
    float2* hs = (float2*)(smem + HS_OFF);           // [4][256] duplicated h

    const int tid  = threadIdx.x;
    const int n    = tid & 255;                      // gate feature
    const int rp   = tid >> 8;                       // row pair 0/1
    const int rank = blockIdx.x & (CLSZ - 1);
    const int rowA = blockIdx.x * RR + 2 * rp;
    const int rowB = rowA + 1;

    const uint32_t smem_b = smem_u32(smem);
    const uint32_t ws_b   = smem_b;
    const uint32_t fb0    = smem_b + MB_OFF;         // full barriers (3 x 8B)
    const uint32_t eb0    = smem_b + MB_OFF + 32;    // empty barriers (3 x 8B)

    if (tid == 0) {
        #pragma unroll
        for (int i = 0; i < NSLOT; i++) {
            mbar_init(fb0 + 8*i, 1);                 // arrive: own expect_tx
            mbar_init(eb0 + 8*i, CLSZ);              // arrives: 8 consumer CTAs
        }
    }

    // h(0) = c(0) = state
    float cA = g_state[rowA * 256 + n];
    float cB = g_state[rowB * 256 + n];
    hs[(2*rp)     * 256 + n] = make_float2(cA, cA);
    hs[(2*rp + 1) * 256 + n] = make_float2(cB, cB);
    __syncthreads();

    // All mbarriers initialized cluster-wide before any multicast
    asm volatile("barrier.cluster.arrive.aligned;" ::: "memory");
    asm volatile("barrier.cluster.wait.aligned;"   ::: "memory");

    const char* wsrc = (const char*)g_W4;

    // producer state (thread 0 only uses these)
    int pq = 0, pslot = 0, pph = 1;
    // consumer state
    int cslot = 0, cph = 0;

    // prologue: produce 2 stages ahead
    if (tid == 0) {
        #pragma unroll
        for (int p = 0; p < 2; p++) {
            mbar_wait_rlx(eb0 + 8*pslot, pph);
            mbar_expect(fb0 + 8*pslot, STG_BYTES);
            bulk_mc(ws_b + pslot*STG_BYTES + rank*SLICE_BYTES,
                    wsrc + (pq & (SPS-1))*STG_BYTES + rank*SLICE_BYTES,
                    SLICE_BYTES, fb0 + 8*pslot, (uint16_t)0xFF);
            pq++;
            if (++pslot == NSLOT) { pslot = 0; pph ^= 1; }
        }
    }

    const float2* hA = hs + (2*rp) * 256;
    const float2* hB = hs + (2*rp + 1) * 256;

    #pragma unroll 1
    for (int t = 0; t < TSTEPS; t++) {
        // G prefetch (consumed at step end; ~8K cyc of cover)
        const float* GpA = g_G + ((size_t)t * BATCH + rowA) * G4 + n;
        const float* GpB = GpA + G4;
        const float giA = GpA[0], gfA = GpA[256], ggA = GpA[512], goA = GpA[768];
        const float giB = GpB[0], gfB = GpB[256], ggB = GpB[512], goB = GpB[768];

        unsigned long long aifA = 0, agoA = 0, aifB = 0, agoB = 0;

        #pragma unroll 1
        for (int s = 0; s < SPS; s++) {
            // produce stage pq (2 ahead of consumption)
            if (tid == 0 && pq < TOTSTG) {
                mbar_wait_rlx(eb0 + 8*pslot, pph);
                mbar_expect(fb0 + 8*pslot, STG_BYTES);
                bulk_mc(ws_b + pslot*STG_BYTES + rank*SLICE_BYTES,
                        wsrc + (pq & (SPS-1))*STG_BYTES + rank*SLICE_BYTES,
                        SLICE_BYTES, fb0 + 8*pslot, (uint16_t)0xFF);
                pq++;
                if (++pslot == NSLOT) { pslot = 0; pph ^= 1; }
            }

            // consume
            mbar_wait_acq(fb0 + 8*cslot, cph);

            const float4* stg = ws + cslot * (KPS * 256) + n;
            const int ks = s * KPS;
            #pragma unroll
            for (int i = 0; i < KPS/2; i++) {
                F4U w0, w1, a4, b4;
                w0.f = stg[(2*i)   * 256];
                w1.f = stg[(2*i+1) * 256];
                a4.f = *(const float4*)(hA + ks + 2*i);
                b4.f = *(const float4*)(hB + ks + 2*i);
                fma2(aifA, w0.u.x, a4.u.x); fma2(agoA, w0.u.y, a4.u.x);
                fma2(aifA, w1.u.x, a4.u.y); fma2(agoA, w1.u.y, a4.u.y);
                fma2(aifB, w0.u.x, b4.u.x); fma2(agoB, w0.u.y, b4.u.x);
                fma2(aifB, w1.u.x, b4.u.y); fma2(agoB, w1.u.y, b4.u.y);
            }

            __syncthreads();   // all threads done with this slot (and, at s==15, with old h)

            if (tid == 32) {   // warp 1 handles empty arrivals (role split)
                #pragma unroll
                for (int j = 0; j < CLSZ; j++) mbar_arrive_rank(eb0 + 8*cslot, j);
            }
            if (++cslot == NSLOT) { cslot = 0; cph ^= 1; }
        }

        // gate math + h update (thread-local; old-h reads all done pre-sync)
        {
            F2U eifA, egoA, eifB, egoB;
            eifA.u = aifA; egoA.u = agoA; eifB.u = aifB; egoB.u = agoB;
            const float ziA = eifA.f.x + giA, zfA = eifA.f.y + gfA;
            const float zgA = egoA.f.x + ggA, zoA = egoA.f.y + goA;
            const float ziB = eifB.f.x + giB, zfB = eifB.f.y + gfB;
            const float zgB = egoB.f.x + ggB, zoB = egoB.f.y + goB;
            cA = sigm(zfA) * cA + sigm(ziA) * tanha(zgA);
            cB = sigm(zfB) * cB + sigm(ziB) * tanha(zgB);
            const float hnA = sigm(zoA) * tanha(cA);
            const float hnB = sigm(zoB) * tanha(cB);
            hs[(2*rp)     * 256 + n] = make_float2(hnA, hnA);
            hs[(2*rp + 1) * 256 + n] = make_float2(hnB, hnB);
        }
        __syncthreads();       // new h visible before next step's stage 0
    }

    g_h[rowA * 256 + n] = hs[(2*rp)     * 256 + n].x;
    g_h[rowB * 256 + n] = hs[(2*rp + 1) * 256 + n].x;

    // no CTA may exit while peers' multicast/arrives into its smem are in flight
    asm volatile("barrier.cluster.arrive.aligned;" ::: "memory");
    asm volatile("barrier.cluster.wait.aligned;"   ::: "memory");
}

// ---------------------------------------------------------------------------
// K4: out = relu(h @ Wo + bo), [512,1]. One warp per batch row.
// ---------------------------------------------------------------------------
__global__ void out_kernel(const float* __restrict__ Wo,
                           const float* __restrict__ bo,
                           float* __restrict__ out)
{
    const int b = blockIdx.x;
    const int lane = threadIdx.x;
    float s = 0.f;
    #pragma unroll
    for (int k = lane; k < 256; k += 32) s += g_h[b*256 + k] * Wo[k];
    #pragma unroll
    for (int off = 16; off; off >>= 1) s += __shfl_down_sync(0xffffffffu, s, off);
    if (lane == 0) out[b] = fmaxf(s + bo[0], 0.f);
}

// ---------------------------------------------------------------------------
extern "C" void kernel_launch(void* const* d_in, const int* in_sizes, int n_in,
                              void* d_out, int out_size)
{
    const float* motion = (const float*)d_in[0];
    const float* robot  = (const float*)d_in[1];
    const float* osr    = (const float*)d_in[2];
    const float* osi    = (const float*)d_in[3];
    const float* hist   = (const float*)d_in[4];
    const float* act    = (const float*)d_in[5];
    const float* orr_   = (const float*)d_in[6];
    const float* ori_   = (const float*)d_in[7];
    const float* Wm  = (const float*)d_in[8];
    const float* bm  = (const float*)d_in[9];
    const float* Wr  = (const float*)d_in[10];
    const float* br  = (const float*)d_in[11];
    const float* Wre = (const float*)d_in[12];
    const float* bre = (const float*)d_in[13];
    const float* Wim = (const float*)d_in[14];
    const float* bim = (const float*)d_in[15];
    const float* Wc  = (const float*)d_in[16];
    const float* bc  = (const float*)d_in[17];
    const float* Wk  = (const float*)d_in[18];
    const float* Wrk = (const float*)d_in[19];
    const float* bl  = (const float*)d_in[20];
    const float* Wo  = (const float*)d_in[21];
    const float* bo  = (const float*)d_in[22];
    float* out = (float*)d_out;

    static int smem_set = 0;
    if (!smem_set) {
        cudaFuncSetAttribute(recur_mc_kernel,
                             cudaFuncAttributeMaxDynamicSharedMemorySize, RSMEM);
        smem_set = 1;
    }

    reformat_wrk<<<256, 256>>>(Wrk);

    preamble_kernel<<<BATCH, 256>>>(motion, robot, osr, osi, orr_, ori_,
                                    Wm, bm, Wr, br, Wre, bre, Wim, bim, Wc, bc);

    dim3 g2(G4 / 128, (TSTEPS * BATCH) / 128);   // (8, 1020)
    xwk_kernel<<<g2, 256>>>(hist, act, Wk, bl);

    recur_mc_kernel<<<RC, RTH, RSMEM>>>();

    out_kernel<<<BATCH, 32>>>(Wo, bo, out);
}

// round 7
// speedup vs baseline: 2.4739x; 2.4739x over previous
#include <cuda_runtime.h>
#include <cuda_fp16.h>
#include <math.h>
#include <stdint.h>

#define BATCH   512
#define STEPS   128
#define TSTEPS  255          // 127 history + 128 action
#define DIN     256
#define UDIM    256
#define G4      1024         // 4*UDIM
#define RROWS   4            // batch rows per recurrence CTA
#define RCTAS   (BATCH / RROWS)                 // 128

// Scratch (static device allocations — no cudaMalloc anywhere)
__device__ float  g_state[BATCH * UDIM];
__device__ float  g_h[BATCH * UDIM];
__device__ float  g_G[(size_t)TSTEPS * BATCH * G4];   // 535 MB: x@Wk + bl, [t][b][4U]
__device__ uint4  g_Whp[128 * 256];   // fp16 Wrk: k-pair x n -> {(wi,wf),(wg,wo)}k, {..}k+1

// ---------------------------------------------------------------------------
// f32x2 packed-FMA helpers (sm_103a FFMA2 — only reachable via PTX)
// ---------------------------------------------------------------------------
union F2U { float2 f; unsigned long long u; };
union F4U { float4 f; ulonglong2 u; };

__device__ __forceinline__ void fma2(unsigned long long& d,
                                     unsigned long long a,
                                     unsigned long long b)
{
    asm("fma.rn.f32x2 %0, %1, %2, %0;" : "+l"(d) : "l"(a), "l"(b));
}
__device__ __forceinline__ unsigned long long dup2(float x)
{
    F2U t; t.f = make_float2(x, x); return t.u;
}
__device__ __forceinline__ float tanha(float x)
{
    float y; asm("tanh.approx.f32 %0, %1;" : "=f"(y) : "f"(x)); return y;
}
__device__ __forceinline__ float sigm(float x)
{
    return fmaf(0.5f, tanha(0.5f * x), 0.5f);
}
__device__ __forceinline__ unsigned long long h2f2(uint32_t h2bits)
{
    __half2 h = *(__half2*)&h2bits;
    F2U t; t.f = __half22float2(h);
    return t.u;
}

// ---------------------------------------------------------------------------
// K0: reformat Wrk [256,1024] -> fp16 k-pair layout:
// g_Whp[kk*256 + n] = { h2(wi,wf)@k=2kk, h2(wg,wo)@k=2kk, h2(wi,wf)@k=2kk+1, h2(wg,wo)@k=2kk+1 }
// ---------------------------------------------------------------------------
__global__ void reformat_wrk(const float* __restrict__ Wrk)
{
    const int idx = blockIdx.x * 256 + threadIdx.x;   // 32768
    const int kk = idx >> 8, n = idx & 255;
    const float* w0 = Wrk + (2*kk)     * G4 + n;
    const float* w1 = Wrk + (2*kk + 1) * G4 + n;
    __half2 a = __floats2half2_rn(w0[0],   w0[256]);
    __half2 b = __floats2half2_rn(w0[512], w0[768]);
    __half2 c = __floats2half2_rn(w1[0],   w1[256]);
    __half2 d = __floats2half2_rn(w1[512], w1[768]);
    uint4 out;
    out.x = *(uint32_t*)&a; out.y = *(uint32_t*)&b;
    out.z = *(uint32_t*)&c; out.w = *(uint32_t*)&d;
    g_Whp[idx] = out;
}

// ---------------------------------------------------------------------------
// K1: preamble — ms/rs/re/im + combine -> state [512,256]
// ---------------------------------------------------------------------------
__global__ void __launch_bounds__(256) preamble_kernel(
    const float* __restrict__ motion, const float* __restrict__ robot,
    const float* __restrict__ osr,    const float* __restrict__ osi,
    const float* __restrict__ orr_,   const float* __restrict__ ori_,
    const float* __restrict__ Wm, const float* __restrict__ bm,
    const float* __restrict__ Wr, const float* __restrict__ br,
    const float* __restrict__ Wre, const float* __restrict__ bre,
    const float* __restrict__ Wim, const float* __restrict__ bim,
    const float* __restrict__ Wc,  const float* __restrict__ bc)
{
    __shared__ float comb[768];
    const int row = blockIdx.x;
    const int n   = threadIdx.x;

    float s = bm[n];
    #pragma unroll 8
    for (int k = 0; k < 64; k++) s += motion[row*64 + k] * Wm[k*256 + n];
    comb[n] = fmaxf(s, 0.f);

    s = br[n];
    #pragma unroll 8
    for (int k = 0; k < 128; k++) s += robot[row*128 + k] * Wr[k*256 + n];
    comb[256 + n] = fmaxf(s, 0.f);

    if (n < 128) {
        float s3 = bre[n];
        #pragma unroll 8
        for (int k = 0; k < 64; k++) s3 += osr [row*64 + k] * Wre[k*128 + n];
        #pragma unroll 8
        for (int k = 0; k < 64; k++) s3 += orr_[row*64 + k] * Wre[(64+k)*128 + n];
        comb[512 + n] = fmaxf(s3, 0.f);
    } else {
        const int m = n - 128;
        float s4 = bim[m];
        #pragma unroll 8
        for (int k = 0; k < 64; k++) s4 += osi [row*64 + k] * Wim[k*128 + m];
        #pragma unroll 8
        for (int k = 0; k < 64; k++) s4 += ori_[row*64 + k] * Wim[(64+k)*128 + m];
        comb[640 + m] = fmaxf(s4, 0.f);
    }
    __syncthreads();

    float s5 = bc[n];
    #pragma unroll 8
    for (int k = 0; k < 768; k++) s5 += comb[k] * Wc[k*256 + n];
    g_state[row*256 + n] = fmaxf(s5, 0.f);
}

// ---------------------------------------------------------------------------
// K2: G = x @ Wk + bl.  M=130560, K=256, N=1024.
// 128x128 tile, BK=16, 256 threads, 8x8 microtile, FFMA2, reg-prefetch.
// ---------------------------------------------------------------------------
__global__ void __launch_bounds__(256, 1) xwk_kernel(
    const float* __restrict__ hist, const float* __restrict__ act,
    const float* __restrict__ Wk,   const float* __restrict__ bl)
{
    __shared__ float As[16][132];
    __shared__ float Bs[16][128];

    const int tid = threadIdx.x;
    const int tx  = tid & 15, ty = tid >> 4;
    const int bm0 = blockIdx.y * 128;
    const int bn0 = blockIdx.x * 128;

    const int ra = tid >> 2;
    const int kc = (tid & 3) * 4;
    const int mA0 = bm0 + ra, mA1 = bm0 + ra + 64;
    const int tA0 = mA0 >> 9, bA0 = mA0 & 511;
    const int tA1 = mA1 >> 9, bA1 = mA1 & 511;
    const float* arow0 = (tA0 < 127)
        ? (hist + ((size_t)bA0 * STEPS + tA0) * DIN)
        : (act  + ((size_t)bA0 * STEPS + (tA0 - 127)) * DIN);
    const float* arow1 = (tA1 < 127)
        ? (hist + ((size_t)bA1 * STEPS + tA1) * DIN)
        : (act  + ((size_t)bA1 * STEPS + (tA1 - 127)) * DIN);

    const int kb = tid >> 4;
    const int nb = (tid & 15) * 4;
    const float* bsrc = Wk + (size_t)kb * G4 + bn0 + nb;

    unsigned long long acc[8][4];
    #pragma unroll
    for (int i = 0; i < 8; i++)
        #pragma unroll
        for (int j = 0; j < 4; j++) acc[i][j] = 0ull;

    float4 a0 = *(const float4*)(arow0 + kc);
    float4 a1 = *(const float4*)(arow1 + kc);
    float4 b0 = *(const float4*)(bsrc);
    float4 b1 = *(const float4*)(bsrc + 64);

    for (int k0 = 0; k0 < 256; k0 += 16) {
        __syncthreads();
        As[kc+0][ra] = a0.x; As[kc+1][ra] = a0.y; As[kc+2][ra] = a0.z; As[kc+3][ra] = a0.w;
        As[kc+0][ra+64] = a1.x; As[kc+1][ra+64] = a1.y; As[kc+2][ra+64] = a1.z; As[kc+3][ra+64] = a1.w;
        *(float4*)&Bs[kb][nb]      = b0;
        *(float4*)&Bs[kb][nb + 64] = b1;
        __syncthreads();

        if (k0 + 16 < 256) {
            a0 = *(const float4*)(arow0 + k0 + 16 + kc);
            a1 = *(const float4*)(arow1 + k0 + 16 + kc);
            b0 = *(const float4*)(bsrc + (size_t)(k0 + 16) * G4);
            b1 = *(const float4*)(bsrc + (size_t)(k0 + 16) * G4 + 64);
        }

        #pragma unroll
        for (int k = 0; k < 16; k++) {
            float4 av0 = *(const float4*)&As[k][ty*8];
            float4 av1 = *(const float4*)&As[k][ty*8 + 4];
            F4U bv0, bv1;
            bv0.f = *(const float4*)&Bs[k][tx*8];
            bv1.f = *(const float4*)&Bs[k][tx*8 + 4];
            unsigned long long bp[4] = { bv0.u.x, bv0.u.y, bv1.u.x, bv1.u.y };
            float afl[8] = { av0.x, av0.y, av0.z, av0.w, av1.x, av1.y, av1.z, av1.w };
            #pragma unroll
            for (int i = 0; i < 8; i++) {
                unsigned long long ad = dup2(afl[i]);
                #pragma unroll
                for (int j = 0; j < 4; j++) fma2(acc[i][j], ad, bp[j]);
            }
        }
    }

    float blv[8];
    #pragma unroll
    for (int j = 0; j < 8; j++) blv[j] = bl[bn0 + tx*8 + j];

    #pragma unroll
    for (int i = 0; i < 8; i++) {
        const int m = bm0 + ty*8 + i;
        float v[8];
        #pragma unroll
        for (int j = 0; j < 4; j++) {
            F2U e; e.u = acc[i][j];
            v[j*2]   = e.f.x + blv[j*2];
            v[j*2+1] = e.f.y + blv[j*2+1];
        }
        float* dst = g_G + (size_t)m * G4 + bn0 + tx*8;
        *(float4*)dst       = make_float4(v[0], v[1], v[2], v[3]);
        *(float4*)(dst + 4) = make_float4(v[4], v[5], v[6], v[7]);
    }
}

// ---------------------------------------------------------------------------
// K3: persistent LSTM recurrence. 128 CTAs x 4 batch rows, 512 threads.
// K-split: warps 0-7 handle k in [0,128), warps 8-15 handle k in [128,256).
// Weight stream in fp16 (half L2 traffic), converted to fp32 in-register,
// FFMA2 math. Partials reduced through smem each step. No cross-CTA sync.
// ---------------------------------------------------------------------------
__global__ void __launch_bounds__(512, 1) recur_kernel()
{
    __shared__ float2 hs2[RROWS][256];        // 8 KB, h duplicated
    __shared__ float4 part[RROWS][256];       // 16 KB, (if.x,if.y,go.x,go.y) partials

    const int tid  = threadIdx.x;
    const int n    = tid & 255;               // gate feature
    const int half = tid >> 8;                // k half: 0 or 1
    const int r0   = blockIdx.x * RROWS;

    float c[RROWS];
    if (half == 0) {
        #pragma unroll
        for (int r = 0; r < RROWS; r++) {
            c[r] = g_state[(r0 + r) * 256 + n];
            hs2[r][n] = make_float2(c[r], c[r]);
        }
    }
    __syncthreads();

    // k-pair pointer: half h owns k-pairs [64h, 64h+64)
    const uint4* wp = g_Whp + (size_t)(half * 64) * 256 + n;
    const int kbase = half * 128;

    for (int t = 0; t < TSTEPS; t++) {
        // hoist G loads (half 0 only) — they land under the k-loop
        float gz[RROWS][4];
        if (half == 0) {
            #pragma unroll
            for (int r = 0; r < RROWS; r++) {
                const float* Gp = g_G + ((size_t)t * BATCH + r0 + r) * G4 + n;
                gz[r][0] = Gp[0];   gz[r][1] = Gp[256];
                gz[r][2] = Gp[512]; gz[r][3] = Gp[768];
            }
        }

        unsigned long long accif[RROWS], accgo[RROWS];
        #pragma unroll
        for (int r = 0; r < RROWS; r++) { accif[r] = 0ull; accgo[r] = 0ull; }

        #pragma unroll 4
        for (int kp = 0; kp < 64; kp++) {
            const uint4 w = wp[(size_t)kp * 256];
            const unsigned long long wif0 = h2f2(w.x);
            const unsigned long long wgo0 = h2f2(w.y);
            const unsigned long long wif1 = h2f2(w.z);
            const unsigned long long wgo1 = h2f2(w.w);
            #pragma unroll
            for (int r = 0; r < RROWS; r++) {
                F4U hh; hh.f = *(const float4*)&hs2[r][kbase + 2*kp];
                fma2(accif[r], wif0, hh.u.x);
                fma2(accgo[r], wgo0, hh.u.x);
                fma2(accif[r], wif1, hh.u.y);
                fma2(accgo[r], wgo1, hh.u.y);
            }
        }

        if (half == 1) {
            #pragma unroll
            for (int r = 0; r < RROWS; r++) {
                F4U p; p.u.x = accif[r]; p.u.y = accgo[r];
                part[r][n] = p.f;
            }
        }
        __syncthreads();   // partials visible; all hs2 reads complete

        if (half == 0) {
            #pragma unroll
            for (int r = 0; r < RROWS; r++) {
                F4U p; p.f = part[r][n];
                F2U eif, ego; eif.u = accif[r]; ego.u = accgo[r];
                const float zi = eif.f.x + p.f.x + gz[r][0];
                const float zf = eif.f.y + p.f.y + gz[r][1];
                const float zg = ego.f.x + p.f.z + gz[r][2];
                const float zo = ego.f.y + p.f.w + gz[r][3];
                const float ig = sigm(zi);
                const float fg = sigm(zf);
                const float gg = tanha(zg);
                const float og = sigm(zo);
                c[r] = fg * c[r] + ig * gg;
                const float h = og * tanha(c[r]);
                hs2[r][n] = make_float2(h, h);
            }
        }
        __syncthreads();   // new h (and freed part) visible to all
    }

    if (half == 0) {
        #pragma unroll
        for (int r = 0; r < RROWS; r++)
            g_h[(r0 + r) * 256 + n] = hs2[r][n].x;
    }
}

// ---------------------------------------------------------------------------
// K4: out = relu(h @ Wo + bo), [512,1]. One warp per batch row.
// ---------------------------------------------------------------------------
__global__ void out_kernel(const float* __restrict__ Wo,
                           const float* __restrict__ bo,
                           float* __restrict__ out)
{
    const int b = blockIdx.x;
    const int lane = threadIdx.x;
    float s = 0.f;
    #pragma unroll
    for (int k = lane; k < 256; k += 32) s += g_h[b*256 + k] * Wo[k];
    #pragma unroll
    for (int off = 16; off; off >>= 1) s += __shfl_down_sync(0xffffffffu, s, off);
    if (lane == 0) out[b] = fmaxf(s + bo[0], 0.f);
}

// ---------------------------------------------------------------------------
extern "C" void kernel_launch(void* const* d_in, const int* in_sizes, int n_in,
                              void* d_out, int out_size)
{
    const float* motion = (const float*)d_in[0];
    const float* robot  = (const float*)d_in[1];
    const float* osr    = (const float*)d_in[2];
    const float* osi    = (const float*)d_in[3];
    const float* hist   = (const float*)d_in[4];
    const float* act    = (const float*)d_in[5];
    const float* orr_   = (const float*)d_in[6];
    const float* ori_   = (const float*)d_in[7];
    const float* Wm  = (const float*)d_in[8];
    const float* bm  = (const float*)d_in[9];
    const float* Wr  = (const float*)d_in[10];
    const float* br  = (const float*)d_in[11];
    const float* Wre = (const float*)d_in[12];
    const float* bre = (const float*)d_in[13];
    const float* Wim = (const float*)d_in[14];
    const float* bim = (const float*)d_in[15];
    const float* Wc  = (const float*)d_in[16];
    const float* bc  = (const float*)d_in[17];
    const float* Wk  = (const float*)d_in[18];
    const float* Wrk = (const float*)d_in[19];
    const float* bl  = (const float*)d_in[20];
    const float* Wo  = (const float*)d_in[21];
    const float* bo  = (const float*)d_in[22];
    float* out = (float*)d_out;

    reformat_wrk<<<128, 256>>>(Wrk);

    preamble_kernel<<<BATCH, 256>>>(motion, robot, osr, osi, orr_, ori_,
                                    Wm, bm, Wr, br, Wre, bre, Wim, bim, Wc, bc);

    dim3 g2(G4 / 128, (TSTEPS * BATCH) / 128);   // (8, 1020)
    xwk_kernel<<<g2, 256>>>(hist, act, Wk, bl);

    recur_kernel<<<RCTAS, 512>>>();

    out_kernel<<<BATCH, 32>>>(Wo, bo, out);
}

// round 8
// speedup vs baseline: 2.4809x; 1.0029x over previous
#include <cuda_runtime.h>
#include <cuda_fp16.h>
#include <math.h>
#include <stdint.h>

#define BATCH   512
#define STEPS   128
#define TSTEPS  255          // 127 history + 128 action
#define DIN     256
#define UDIM    256
#define G4      1024         // 4*UDIM
#define RROWS   4            // batch rows per recurrence CTA
#define RCTAS   (BATCH / RROWS)                 // 128

// Scratch (static device allocations — no cudaMalloc anywhere)
__device__ float  g_state[BATCH * UDIM];
__device__ float  g_h[BATCH * UDIM];
__device__ float  g_G[(size_t)TSTEPS * BATCH * G4];   // 535 MB: x@Wk + bl, [t][b][4U]
__device__ uint4  g_Whp[128 * 256];   // fp16 Wrk: k-pair x n -> {(wi,wf),(wg,wo)}k, {..}k+1

// ---------------------------------------------------------------------------
// f32x2 packed-FMA helpers (sm_103a FFMA2 — only reachable via PTX)
// ---------------------------------------------------------------------------
union F2U { float2 f; unsigned long long u; };
union F4U { float4 f; ulonglong2 u; };

__device__ __forceinline__ void fma2(unsigned long long& d,
                                     unsigned long long a,
                                     unsigned long long b)
{
    asm("fma.rn.f32x2 %0, %1, %2, %0;" : "+l"(d) : "l"(a), "l"(b));
}
__device__ __forceinline__ unsigned long long dup2(float x)
{
    F2U t; t.f = make_float2(x, x); return t.u;
}
__device__ __forceinline__ float tanha(float x)
{
    float y; asm("tanh.approx.f32 %0, %1;" : "=f"(y) : "f"(x)); return y;
}
__device__ __forceinline__ float sigm(float x)
{
    return fmaf(0.5f, tanha(0.5f * x), 0.5f);
}
__device__ __forceinline__ unsigned long long h2f2(uint32_t h2bits)
{
    __half2 h = *(__half2*)&h2bits;
    F2U t; t.f = __half22float2(h);
    return t.u;
}

// ---------------------------------------------------------------------------
// K0: reformat Wrk [256,1024] -> fp16 k-pair layout:
// g_Whp[kk*256 + n] = { h2(wi,wf)@k=2kk, h2(wg,wo)@k=2kk, h2(wi,wf)@k=2kk+1, h2(wg,wo)@k=2kk+1 }
// ---------------------------------------------------------------------------
__global__ void reformat_wrk(const float* __restrict__ Wrk)
{
    const int idx = blockIdx.x * 256 + threadIdx.x;   // 32768
    const int kk = idx >> 8, n = idx & 255;
    const float* w0 = Wrk + (2*kk)     * G4 + n;
    const float* w1 = Wrk + (2*kk + 1) * G4 + n;
    __half2 a = __floats2half2_rn(w0[0],   w0[256]);
    __half2 b = __floats2half2_rn(w0[512], w0[768]);
    __half2 c = __floats2half2_rn(w1[0],   w1[256]);
    __half2 d = __floats2half2_rn(w1[512], w1[768]);
    uint4 out;
    out.x = *(uint32_t*)&a; out.y = *(uint32_t*)&b;
    out.z = *(uint32_t*)&c; out.w = *(uint32_t*)&d;
    g_Whp[idx] = out;
}

// ---------------------------------------------------------------------------
// K1: preamble — ms/rs/re/im + combine -> state [512,256]
// ---------------------------------------------------------------------------
__global__ void __launch_bounds__(256) preamble_kernel(
    const float* __restrict__ motion, const float* __restrict__ robot,
    const float* __restrict__ osr,    const float* __restrict__ osi,
    const float* __restrict__ orr_,   const float* __restrict__ ori_,
    const float* __restrict__ Wm, const float* __restrict__ bm,
    const float* __restrict__ Wr, const float* __restrict__ br,
    const float* __restrict__ Wre, const float* __restrict__ bre,
    const float* __restrict__ Wim, const float* __restrict__ bim,
    const float* __restrict__ Wc,  const float* __restrict__ bc)
{
    __shared__ float comb[768];
    const int row = blockIdx.x;
    const int n   = threadIdx.x;

    float s = bm[n];
    #pragma unroll 8
    for (int k = 0; k < 64; k++) s += motion[row*64 + k] * Wm[k*256 + n];
    comb[n] = fmaxf(s, 0.f);

    s = br[n];
    #pragma unroll 8
    for (int k = 0; k < 128; k++) s += robot[row*128 + k] * Wr[k*256 + n];
    comb[256 + n] = fmaxf(s, 0.f);

    if (n < 128) {
        float s3 = bre[n];
        #pragma unroll 8
        for (int k = 0; k < 64; k++) s3 += osr [row*64 + k] * Wre[k*128 + n];
        #pragma unroll 8
        for (int k = 0; k < 64; k++) s3 += orr_[row*64 + k] * Wre[(64+k)*128 + n];
        comb[512 + n] = fmaxf(s3, 0.f);
    } else {
        const int m = n - 128;
        float s4 = bim[m];
        #pragma unroll 8
        for (int k = 0; k < 64; k++) s4 += osi [row*64 + k] * Wim[k*128 + m];
        #pragma unroll 8
        for (int k = 0; k < 64; k++) s4 += ori_[row*64 + k] * Wim[(64+k)*128 + m];
        comb[640 + m] = fmaxf(s4, 0.f);
    }
    __syncthreads();

    float s5 = bc[n];
    #pragma unroll 8
    for (int k = 0; k < 768; k++) s5 += comb[k] * Wc[k*256 + n];
    g_state[row*256 + n] = fmaxf(s5, 0.f);
}

// ---------------------------------------------------------------------------
// K2: G = x @ Wk + bl.  M=130560, K=256, N=1024.
// 128x128 tile, BK=16, 256 threads, 8x8 microtile, FFMA2, reg-prefetch.
// ---------------------------------------------------------------------------
__global__ void __launch_bounds__(256, 1) xwk_kernel(
    const float* __restrict__ hist, const float* __restrict__ act,
    const float* __restrict__ Wk,   const float* __restrict__ bl)
{
    __shared__ float As[16][132];
    __shared__ float Bs[16][128];

    const int tid = threadIdx.x;
    const int tx  = tid & 15, ty = tid >> 4;
    const int bm0 = blockIdx.y * 128;
    const int bn0 = blockIdx.x * 128;

    const int ra = tid >> 2;
    const int kc = (tid & 3) * 4;
    const int mA0 = bm0 + ra, mA1 = bm0 + ra + 64;
    const int tA0 = mA0 >> 9, bA0 = mA0 & 511;
    const int tA1 = mA1 >> 9, bA1 = mA1 & 511;
    const float* arow0 = (tA0 < 127)
        ? (hist + ((size_t)bA0 * STEPS + tA0) * DIN)
        : (act  + ((size_t)bA0 * STEPS + (tA0 - 127)) * DIN);
    const float* arow1 = (tA1 < 127)
        ? (hist + ((size_t)bA1 * STEPS + tA1) * DIN)
        : (act  + ((size_t)bA1 * STEPS + (tA1 - 127)) * DIN);

    const int kb = tid >> 4;
    const int nb = (tid & 15) * 4;
    const float* bsrc = Wk + (size_t)kb * G4 + bn0 + nb;

    unsigned long long acc[8][4];
    #pragma unroll
    for (int i = 0; i < 8; i++)
        #pragma unroll
        for (int j = 0; j < 4; j++) acc[i][j] = 0ull;

    float4 a0 = *(const float4*)(arow0 + kc);
    float4 a1 = *(const float4*)(arow1 + kc);
    float4 b0 = *(const float4*)(bsrc);
    float4 b1 = *(const float4*)(bsrc + 64);

    for (int k0 = 0; k0 < 256; k0 += 16) {
        __syncthreads();
        As[kc+0][ra] = a0.x; As[kc+1][ra] = a0.y; As[kc+2][ra] = a0.z; As[kc+3][ra] = a0.w;
        As[kc+0][ra+64] = a1.x; As[kc+1][ra+64] = a1.y; As[kc+2][ra+64] = a1.z; As[kc+3][ra+64] = a1.w;
        *(float4*)&Bs[kb][nb]      = b0;
        *(float4*)&Bs[kb][nb + 64] = b1;
        __syncthreads();

        if (k0 + 16 < 256) {
            a0 = *(const float4*)(arow0 + k0 + 16 + kc);
            a1 = *(const float4*)(arow1 + k0 + 16 + kc);
            b0 = *(const float4*)(bsrc + (size_t)(k0 + 16) * G4);
            b1 = *(const float4*)(bsrc + (size_t)(k0 + 16) * G4 + 64);
        }

        #pragma unroll
        for (int k = 0; k < 16; k++) {
            float4 av0 = *(const float4*)&As[k][ty*8];
            float4 av1 = *(const float4*)&As[k][ty*8 + 4];
            F4U bv0, bv1;
            bv0.f = *(const float4*)&Bs[k][tx*8];
            bv1.f = *(const float4*)&Bs[k][tx*8 + 4];
            unsigned long long bp[4] = { bv0.u.x, bv0.u.y, bv1.u.x, bv1.u.y };
            float afl[8] = { av0.x, av0.y, av0.z, av0.w, av1.x, av1.y, av1.z, av1.w };
            #pragma unroll
            for (int i = 0; i < 8; i++) {
                unsigned long long ad = dup2(afl[i]);
                #pragma unroll
                for (int j = 0; j < 4; j++) fma2(acc[i][j], ad, bp[j]);
            }
        }
    }

    float blv[8];
    #pragma unroll
    for (int j = 0; j < 8; j++) blv[j] = bl[bn0 + tx*8 + j];

    #pragma unroll
    for (int i = 0; i < 8; i++) {
        const int m = bm0 + ty*8 + i;
        float v[8];
        #pragma unroll
        for (int j = 0; j < 4; j++) {
            F2U e; e.u = acc[i][j];
            v[j*2]   = e.f.x + blv[j*2];
            v[j*2+1] = e.f.y + blv[j*2+1];
        }
        float* dst = g_G + (size_t)m * G4 + bn0 + tx*8;
        *(float4*)dst       = make_float4(v[0], v[1], v[2], v[3]);
        *(float4*)(dst + 4) = make_float4(v[4], v[5], v[6], v[7]);
    }
}

// ---------------------------------------------------------------------------
// K3: persistent LSTM recurrence. 128 CTAs x 4 batch rows, 512 threads.
// K-split: warps 0-7 handle k in [0,128), warps 8-15 handle k in [128,256).
// Weight stream in fp16 (half L2 traffic), converted to fp32 in-register,
// FFMA2 math. Partials reduced through smem each step. No cross-CTA sync.
// ---------------------------------------------------------------------------
__global__ void __launch_bounds__(512, 1) recur_kernel()
{
    __shared__ float2 hs2[RROWS][256];        // 8 KB, h duplicated
    __shared__ float4 part[RROWS][256];       // 16 KB, (if.x,if.y,go.x,go.y) partials

    const int tid  = threadIdx.x;
    const int n    = tid & 255;               // gate feature
    const int half = tid >> 8;                // k half: 0 or 1
    const int r0   = blockIdx.x * RROWS;

    float c[RROWS];
    if (half == 0) {
        #pragma unroll
        for (int r = 0; r < RROWS; r++) {
            c[r] = g_state[(r0 + r) * 256 + n];
            hs2[r][n] = make_float2(c[r], c[r]);
        }
    }
    __syncthreads();

    // k-pair pointer: half h owns k-pairs [64h, 64h+64)
    const uint4* wp = g_Whp + (size_t)(half * 64) * 256 + n;
    const int kbase = half * 128;

    for (int t = 0; t < TSTEPS; t++) {
        // hoist G loads (half 0 only) — they land under the k-loop
        float gz[RROWS][4];
        if (half == 0) {
            #pragma unroll
            for (int r = 0; r < RROWS; r++) {
                const float* Gp = g_G + ((size_t)t * BATCH + r0 + r) * G4 + n;
                gz[r][0] = Gp[0];   gz[r][1] = Gp[256];
                gz[r][2] = Gp[512]; gz[r][3] = Gp[768];
            }
        }

        unsigned long long accif[RROWS], accgo[RROWS];
        #pragma unroll
        for (int r = 0; r < RROWS; r++) { accif[r] = 0ull; accgo[r] = 0ull; }

        #pragma unroll 4
        for (int kp = 0; kp < 64; kp++) {
            const uint4 w = wp[(size_t)kp * 256];
            const unsigned long long wif0 = h2f2(w.x);
            const unsigned long long wgo0 = h2f2(w.y);
            const unsigned long long wif1 = h2f2(w.z);
            const unsigned long long wgo1 = h2f2(w.w);
            #pragma unroll
            for (int r = 0; r < RROWS; r++) {
                F4U hh; hh.f = *(const float4*)&hs2[r][kbase + 2*kp];
                fma2(accif[r], wif0, hh.u.x);
                fma2(accgo[r], wgo0, hh.u.x);
                fma2(accif[r], wif1, hh.u.y);
                fma2(accgo[r], wgo1, hh.u.y);
            }
        }

        if (half == 1) {
            #pragma unroll
            for (int r = 0; r < RROWS; r++) {
                F4U p; p.u.x = accif[r]; p.u.y = accgo[r];
                part[r][n] = p.f;
            }
        }
        __syncthreads();   // partials visible; all hs2 reads complete

        if (half == 0) {
            #pragma unroll
            for (int r = 0; r < RROWS; r++) {
                F4U p; p.f = part[r][n];
                F2U eif, ego; eif.u = accif[r]; ego.u = accgo[r];
                const float zi = eif.f.x + p.f.x + gz[r][0];
                const float zf = eif.f.y + p.f.y + gz[r][1];
                const float zg = ego.f.x + p.f.z + gz[r][2];
                const float zo = ego.f.y + p.f.w + gz[r][3];
                const float ig = sigm(zi);
                const float fg = sigm(zf);
                const float gg = tanha(zg);
                const float og = sigm(zo);
                c[r] = fg * c[r] + ig * gg;
                const float h = og * tanha(c[r]);
                hs2[r][n] = make_float2(h, h);
            }
        }
        __syncthreads();   // new h (and freed part) visible to all
    }

    if (half == 0) {
        #pragma unroll
        for (int r = 0; r < RROWS; r++)
            g_h[(r0 + r) * 256 + n] = hs2[r][n].x;
    }
}

// ---------------------------------------------------------------------------
// K4: out = relu(h @ Wo + bo), [512,1]. One warp per batch row.
// ---------------------------------------------------------------------------
__global__ void out_kernel(const float* __restrict__ Wo,
                           const float* __restrict__ bo,
                           float* __restrict__ out)
{
    const int b = blockIdx.x;
    const int lane = threadIdx.x;
    float s = 0.f;
    #pragma unroll
    for (int k = lane; k < 256; k += 32) s += g_h[b*256 + k] * Wo[k];
    #pragma unroll
    for (int off = 16; off; off >>= 1) s += __shfl_down_sync(0xffffffffu, s, off);
    if (lane == 0) out[b] = fmaxf(s + bo[0], 0.f);
}

// ---------------------------------------------------------------------------
extern "C" void kernel_launch(void* const* d_in, const int* in_sizes, int n_in,
                              void* d_out, int out_size)
{
    const float* motion = (const float*)d_in[0];
    const float* robot  = (const float*)d_in[1];
    const float* osr    = (const float*)d_in[2];
    const float* osi    = (const float*)d_in[3];
    const float* hist   = (const float*)d_in[4];
    const float* act    = (const float*)d_in[5];
    const float* orr_   = (const float*)d_in[6];
    const float* ori_   = (const float*)d_in[7];
    const float* Wm  = (const float*)d_in[8];
    const float* bm  = (const float*)d_in[9];
    const float* Wr  = (const float*)d_in[10];
    const float* br  = (const float*)d_in[11];
    const float* Wre = (const float*)d_in[12];
    const float* bre = (const float*)d_in[13];
    const float* Wim = (const float*)d_in[14];
    const float* bim = (const float*)d_in[15];
    const float* Wc  = (const float*)d_in[16];
    const float* bc  = (const float*)d_in[17];
    const float* Wk  = (const float*)d_in[18];
    const float* Wrk = (const float*)d_in[19];
    const float* bl  = (const float*)d_in[20];
    const float* Wo  = (const float*)d_in[21];
    const float* bo  = (const float*)d_in[22];
    float* out = (float*)d_out;

    reformat_wrk<<<128, 256>>>(Wrk);

    preamble_kernel<<<BATCH, 256>>>(motion, robot, osr, osi, orr_, ori_,
                                    Wm, bm, Wr, br, Wre, bre, Wim, bim, Wc, bc);

    dim3 g2(G4 / 128, (TSTEPS * BATCH) / 128);   // (8, 1020)
    xwk_kernel<<<g2, 256>>>(hist, act, Wk, bl);

    recur_kernel<<<RCTAS, 512>>>();

    out_kernel<<<BATCH, 32>>>(Wo, bo, out);
}